// round 16
// baseline (speedup 1.0000x reference)
#include <cuda_runtime.h>
#include <cuda_bf16.h>
#include <math_constants.h>
#include <cstdint>

// VectorQuantizer: mma.sync (HMMA) filter + exact reference-chain rescore.
//   Filter: D = A@B^T, A=[z_hi|z_lo|z_hi], B=[e_hi|e_hi|e_lo] bf16, K=192,
//           fp32 accum -> |dot err| <~ 4e-7. Top-4 candidates per row.
//   Rescore (bit-exact reference arithmetic): dot = sequential fma.rn k=0..63;
//           zsq/csq = seq rnd(mul)+rnd(add); dist = rnd(rnd(zsq-2dot)+csq);
//           argmin strict <, lower index on ties.
//   out = rnd(z + rnd(q-z)); loss = 1.25*mean((q-z)^2) (exact fixed-point).
// tcgen05 is rejected by the harness's compute_103 (non-'a') PTX target;
// mma.sync/ldmatrix are baseline PTX and compile fine.

#define NROWS   65536
#define DIM     64
#define NCODES  1024
#define TPB     128
#define MTILE   128
#define NTILE   128
#define NTILES  (NCODES / NTILE)     // 8
#define NBLOCKS (NROWS / MTILE)      // 512
#define KSPLIT  192
#define KSTEPS  (KSPLIT / 16)        // 12
#define KPAD_B  400                  // padded row stride in bytes (200 bf16)

// dynamic smem layout (bytes)
#define OFF_A    0
#define OFF_B    (MTILE * KPAD_B)                 // 51200
#define OFF_CSQ  (OFF_B + NTILE * KPAD_B)         // 102400
#define OFF_CAND (OFF_CSQ + NTILE * 4)            // 102912
#define OFF_IDX  (OFF_CAND + MTILE * 4 * 4)       // 104960
#define OFF_RED  (OFF_IDX + MTILE * 4)            // 105472
#define SMEM_TOTAL (OFF_RED + 64)                 // 105536 -> 2 blocks/SM

typedef unsigned long long u64;

__device__ uint32_t     g_Bsplit[NCODES * 96];  // [c][96 u32]: hi|hi|lo pairs
__device__ float        g_ctable[NCODES];       // exact ||e||^2 chains
__device__ u64          g_accum = 0;
__device__ unsigned int g_done  = 0;

struct Top4 { float m0, m1, m2, m3; int i0, i1, i2, i3; };

__device__ __forceinline__ void t4_init(Top4& t) {
    t.m0 = t.m1 = t.m2 = t.m3 = CUDART_INF_F;
    t.i0 = t.i1 = t.i2 = t.i3 = 0;
}
__device__ __forceinline__ void t4_insert(Top4& t, float s, int c) {
    if (s < t.m3) {
        if (s < t.m2) {
            t.m3 = t.m2; t.i3 = t.i2;
            if (s < t.m1) {
                t.m2 = t.m1; t.i2 = t.i1;
                if (s < t.m0) { t.m1 = t.m0; t.i1 = t.i0; t.m0 = s; t.i0 = c; }
                else          { t.m1 = s; t.i1 = c; }
            } else { t.m2 = s; t.i2 = c; }
        } else { t.m3 = s; t.i3 = c; }
    }
}
__device__ __forceinline__ void t4_merge_xor(Top4& t, int mask) {
    float a0 = __shfl_xor_sync(0xffffffffu, t.m0, mask);
    float a1 = __shfl_xor_sync(0xffffffffu, t.m1, mask);
    float a2 = __shfl_xor_sync(0xffffffffu, t.m2, mask);
    float a3 = __shfl_xor_sync(0xffffffffu, t.m3, mask);
    int   b0 = __shfl_xor_sync(0xffffffffu, t.i0, mask);
    int   b1 = __shfl_xor_sync(0xffffffffu, t.i1, mask);
    int   b2 = __shfl_xor_sync(0xffffffffu, t.i2, mask);
    int   b3 = __shfl_xor_sync(0xffffffffu, t.i3, mask);
    t4_insert(t, a0, b0); t4_insert(t, a1, b1);
    t4_insert(t, a2, b2); t4_insert(t, a3, b3);
}

__device__ __forceinline__ uint32_t smem_u32(const void* p) {
    uint32_t a;
    asm("{ .reg .u64 t; cvta.to.shared.u64 t, %1; cvt.u32.u64 %0, t; }" : "=r"(a) : "l"(p));
    return a;
}
__device__ __forceinline__ void ldsm_x4(uint32_t addr, uint32_t& r0, uint32_t& r1,
                                        uint32_t& r2, uint32_t& r3) {
    asm volatile("ldmatrix.sync.aligned.m8n8.x4.shared.b16 {%0,%1,%2,%3}, [%4];"
                 : "=r"(r0), "=r"(r1), "=r"(r2), "=r"(r3) : "r"(addr));
}
__device__ __forceinline__ void mma16816(float* d, const uint32_t* a,
                                         uint32_t b0, uint32_t b1) {
    asm volatile("mma.sync.aligned.m16n8k16.row.col.f32.bf16.bf16.f32 "
                 "{%0,%1,%2,%3}, {%4,%5,%6,%7}, {%8,%9}, {%0,%1,%2,%3};"
                 : "+f"(d[0]), "+f"(d[1]), "+f"(d[2]), "+f"(d[3])
                 : "r"(a[0]), "r"(a[1]), "r"(a[2]), "r"(a[3]), "r"(b0), "r"(b1));
}
__device__ __forceinline__ void split_pair(float x0, float x1, uint32_t& hp, uint32_t& lp) {
    __nv_bfloat16 h0 = __float2bfloat16(x0), h1 = __float2bfloat16(x1);
    float f0 = __bfloat162float(h0), f1 = __bfloat162float(h1);
    __nv_bfloat16 l0 = __float2bfloat16(x0 - f0), l1 = __float2bfloat16(x1 - f1);
    hp = (uint32_t)__bfloat16_as_ushort(h0) | ((uint32_t)__bfloat16_as_ushort(h1) << 16);
    lp = (uint32_t)__bfloat16_as_ushort(l0) | ((uint32_t)__bfloat16_as_ushort(l1) << 16);
}

// Prep: split codebook to bf16 [hi|hi|lo] u32 pairs + exact csq chains.
__global__ void vq_prep_kernel(const float* __restrict__ emb) {
    int c = blockIdx.x * blockDim.x + threadIdx.x;
    if (c >= NCODES) return;
    const float* e = emb + (size_t)c * DIM;
    float acc = 0.f;
    uint32_t* dst = g_Bsplit + (size_t)c * 96;
#pragma unroll
    for (int p = 0; p < 32; p++) {
        float x0 = e[2 * p], x1 = e[2 * p + 1];
        acc = __fadd_rn(acc, __fmul_rn(x0, x0));
        acc = __fadd_rn(acc, __fmul_rn(x1, x1));
        uint32_t hp, lp; split_pair(x0, x1, hp, lp);
        dst[p] = hp; dst[32 + p] = hp; dst[64 + p] = lp;
    }
    g_ctable[c] = acc;
}

__global__ __launch_bounds__(TPB, 2) void vq_mma_kernel(
    const float* __restrict__ z,
    const float* __restrict__ emb,
    float* __restrict__ out,
    int out_size)
{
    extern __shared__ char smem[];
    float*  s_csq  = (float*)(smem + OFF_CSQ);
    int*    s_cand = (int*)(smem + OFF_CAND);
    int*    s_idx  = (int*)(smem + OFF_IDX);
    double* s_red  = (double*)(smem + OFF_RED);
    const uint32_t sbase = smem_u32(smem);

    const int tid  = threadIdx.x;
    const int lane = tid & 31;
    const int w    = tid >> 5;
    const int row  = blockIdx.x * MTILE + tid;

    // Stage A: split this thread's z row -> [hi(k0-63)|lo(k64-127)|hi(k128-191)]
    {
        const float4* zp = (const float4*)(z + (size_t)row * DIM);
        char* arow = smem + OFF_A + (size_t)tid * KPAD_B;
#pragma unroll
        for (int i = 0; i < DIM / 4; i++) {
            float4 v = zp[i];
            uint32_t hp0, lp0, hp1, lp1;
            split_pair(v.x, v.y, hp0, lp0);
            split_pair(v.z, v.w, hp1, lp1);
            ((uint32_t*)arow)[2 * i]          = hp0;
            ((uint32_t*)arow)[2 * i + 1]      = hp1;
            ((uint32_t*)arow)[32 + 2 * i]     = lp0;
            ((uint32_t*)arow)[32 + 2 * i + 1] = lp1;
            ((uint32_t*)arow)[64 + 2 * i]     = hp0;
            ((uint32_t*)arow)[64 + 2 * i + 1] = hp1;
        }
    }
    __syncthreads();

    // Load A fragments into registers: 2 m16-tiles x 12 k16-steps x 4 regs.
    uint32_t AF[2][KSTEPS][4];
#pragma unroll
    for (int mt = 0; mt < 2; mt++) {
        const int r0 = w * 32 + mt * 16;
#pragma unroll
        for (int s = 0; s < KSTEPS; s++) {
            uint32_t addr = sbase + OFF_A
                + (uint32_t)(r0 + (lane & 7) + 8 * ((lane >> 3) & 1)) * KPAD_B
                + (uint32_t)(16 * s + 8 * (lane >> 4)) * 2;
            ldsm_x4(addr, AF[mt][s][0], AF[mt][s][1], AF[mt][s][2], AF[mt][s][3]);
        }
    }

    Top4 t0, t1, t2, t3;
    t4_init(t0); t4_init(t1); t4_init(t2); t4_init(t3);

    for (int nt8 = 0; nt8 < NTILES; nt8++) {
        // Stage B chunk (128 codes x 96 u32, padded rows) + csq slice.
        {
            const uint32_t* src = g_Bsplit + (size_t)nt8 * NTILE * 96;
            for (int u = tid; u < NTILE * 96; u += TPB) {
                int r = u / 96, c = u - r * 96;
                *(uint32_t*)(smem + OFF_B + (size_t)r * KPAD_B + (size_t)c * 4) = src[u];
            }
            if (tid < NTILE) s_csq[tid] = g_ctable[nt8 * NTILE + tid];
        }
        __syncthreads();

        for (int nt = 0; nt < NTILE / 8; nt++) {
            const int n0 = nt * 8;
            // B fragments: 12 k-steps x 2 regs via 6 ldmatrix.x4.
            uint32_t BF[KSTEPS][2];
#pragma unroll
            for (int sp = 0; sp < KSTEPS / 2; sp++) {
                uint32_t addr = sbase + OFF_B
                    + (uint32_t)(n0 + (lane & 7)) * KPAD_B
                    + (uint32_t)(32 * sp + 8 * (lane >> 3)) * 2;
                ldsm_x4(addr, BF[2 * sp][0], BF[2 * sp][1],
                              BF[2 * sp + 1][0], BF[2 * sp + 1][1]);
            }
            float D0[4] = {0.f, 0.f, 0.f, 0.f};
            float D1[4] = {0.f, 0.f, 0.f, 0.f};
#pragma unroll
            for (int s = 0; s < KSTEPS; s++) {
                mma16816(D0, AF[0][s], BF[s][0], BF[s][1]);
                mma16816(D1, AF[1][s], BF[s][0], BF[s][1]);
            }
            // Scores: csq - 2*dot; fold into per-thread top-4 (4 row-slots).
            const int nl = n0 + 2 * (lane & 3);
            const float c0 = s_csq[nl], c1 = s_csq[nl + 1];
            const int cg = nt8 * NTILE + nl;
            t4_insert(t0, __fmaf_rn(-2.f, D0[0], c0), cg);
            t4_insert(t0, __fmaf_rn(-2.f, D0[1], c1), cg + 1);
            t4_insert(t1, __fmaf_rn(-2.f, D0[2], c0), cg);
            t4_insert(t1, __fmaf_rn(-2.f, D0[3], c1), cg + 1);
            t4_insert(t2, __fmaf_rn(-2.f, D1[0], c0), cg);
            t4_insert(t2, __fmaf_rn(-2.f, D1[1], c1), cg + 1);
            t4_insert(t3, __fmaf_rn(-2.f, D1[2], c0), cg);
            t4_insert(t3, __fmaf_rn(-2.f, D1[3], c1), cg + 1);
        }
        __syncthreads();   // before restaging B
    }

    // Merge top-4 across the 4 lanes of each quad (same rows).
    t4_merge_xor(t0, 1); t4_merge_xor(t0, 2);
    t4_merge_xor(t1, 1); t4_merge_xor(t1, 2);
    t4_merge_xor(t2, 1); t4_merge_xor(t2, 2);
    t4_merge_xor(t3, 1); t4_merge_xor(t3, 2);
    if ((lane & 3) == 0) {
        int rbase = w * 32 + (lane >> 2);
        int* c0p = s_cand + (rbase)      * 4;
        int* c1p = s_cand + (rbase + 8)  * 4;
        int* c2p = s_cand + (rbase + 16) * 4;
        int* c3p = s_cand + (rbase + 24) * 4;
        c0p[0] = t0.i0; c0p[1] = t0.i1; c0p[2] = t0.i2; c0p[3] = t0.i3;
        c1p[0] = t1.i0; c1p[1] = t1.i1; c1p[2] = t1.i2; c1p[3] = t1.i3;
        c2p[0] = t2.i0; c2p[1] = t2.i1; c2p[2] = t2.i2; c2p[3] = t2.i3;
        c3p[0] = t3.i0; c3p[1] = t3.i1; c3p[2] = t3.i2; c3p[3] = t3.i3;
    }
    __syncthreads();

    // Exact rescore with the reference arithmetic (thread = row).
    {
        const float4* zp = (const float4*)(z + (size_t)row * DIM);
        float zr[DIM];
        float zsq = 0.f;
#pragma unroll
        for (int i = 0; i < DIM / 4; i++) {
            float4 v = zp[i];
            zr[4 * i] = v.x; zr[4 * i + 1] = v.y;
            zr[4 * i + 2] = v.z; zr[4 * i + 3] = v.w;
            zsq = __fadd_rn(zsq, __fmul_rn(v.x, v.x));
            zsq = __fadd_rn(zsq, __fmul_rn(v.y, v.y));
            zsq = __fadd_rn(zsq, __fmul_rn(v.z, v.z));
            zsq = __fadd_rn(zsq, __fmul_rn(v.w, v.w));
        }
        float bD = CUDART_INF_F; int bI = 0x7fffffff;
#pragma unroll
        for (int j = 0; j < 4; j++) {
            int c = s_cand[tid * 4 + j];
            const float4* e4 = (const float4*)(emb + (size_t)c * DIM);
            float dot = 0.f;
#pragma unroll
            for (int i = 0; i < DIM / 4; i++) {
                float4 v = e4[i];
                dot = __fmaf_rn(zr[4 * i],     v.x, dot);
                dot = __fmaf_rn(zr[4 * i + 1], v.y, dot);
                dot = __fmaf_rn(zr[4 * i + 2], v.z, dot);
                dot = __fmaf_rn(zr[4 * i + 3], v.w, dot);
            }
            float t = __fadd_rn(zsq, __fmul_rn(dot, -2.0f));
            float D = __fadd_rn(t, g_ctable[c]);
            if (D < bD || (D == bD && c < bI)) { bD = D; bI = c; }
        }
        s_idx[tid] = bI;
    }
    __syncthreads();

    // Output: out = rnd(z + rnd(q - z)); loss partial in double.
    double lsum = 0.0;
    {
        const float4* zb = (const float4*)(z + (size_t)blockIdx.x * MTILE * DIM);
        const float4* eb = (const float4*)emb;
        float4* ob = (float4*)out + (size_t)blockIdx.x * MTILE * (DIM / 4);
        for (int idx = tid; idx < MTILE * (DIM / 4); idx += TPB) {
            int r = idx >> 4, c4 = idx & 15;
            float4 zv = zb[idx];
            float4 qv = eb[(size_t)s_idx[r] * (DIM / 4) + c4];
            float4 dv, ov;
            dv.x = __fadd_rn(qv.x, -zv.x);  ov.x = __fadd_rn(zv.x, dv.x);
            dv.y = __fadd_rn(qv.y, -zv.y);  ov.y = __fadd_rn(zv.y, dv.y);
            dv.z = __fadd_rn(qv.z, -zv.z);  ov.z = __fadd_rn(zv.z, dv.z);
            dv.w = __fadd_rn(qv.w, -zv.w);  ov.w = __fadd_rn(zv.w, dv.w);
            lsum += (double)__fmul_rn(dv.x, dv.x) + (double)__fmul_rn(dv.y, dv.y)
                  + (double)__fmul_rn(dv.z, dv.z) + (double)__fmul_rn(dv.w, dv.w);
            ob[idx] = ov;
        }
    }
#pragma unroll
    for (int o = 16; o > 0; o >>= 1)
        lsum += __shfl_down_sync(0xffffffffu, lsum, o);
    if ((tid & 31) == 0) s_red[tid >> 5] = lsum;
    __syncthreads();
    if (tid == 0) {
        double t = 0.0;
#pragma unroll
        for (int i = 0; i < TPB / 32; i++) t += s_red[i];
        u64 q = (u64)(t * 1099511627776.0 + 0.5);   // 2^40 fixed point, exact
        atomicAdd(&g_accum, q);
        __threadfence();
        unsigned int done = atomicAdd(&g_done, 1u);
        if (done == NBLOCKS - 1) {
            u64 total = *(volatile u64*)&g_accum;
            double s = (double)total * (1.0 / 1099511627776.0);
            float mf = (float)(s / (double)((size_t)NROWS * DIM));
            out[out_size - 1] = __fadd_rn(__fmul_rn(0.25f, mf), mf);
            *(volatile u64*)&g_accum = 0ull;
            *(volatile unsigned int*)&g_done = 0u;
        }
    }
}

extern "C" void kernel_launch(void* const* d_in, const int* in_sizes, int n_in,
                              void* d_out, int out_size) {
    const float* z   = (const float*)d_in[0];
    const float* emb = (const float*)d_in[1];
    if (n_in >= 2 && in_sizes[0] == NCODES * DIM && in_sizes[1] == NROWS * DIM) {
        const float* t = z; z = emb; emb = t;
    }
    float* out = (float*)d_out;

    cudaFuncSetAttribute(vq_mma_kernel,
                         cudaFuncAttributeMaxDynamicSharedMemorySize, SMEM_TOTAL);

    vq_prep_kernel<<<(NCODES + 127) / 128, 128>>>(emb);
    vq_mma_kernel<<<NBLOCKS, TPB, SMEM_TOTAL>>>(z, emb, out, out_size);
}